// round 16
// baseline (speedup 1.0000x reference)
#include <cuda_runtime.h>
#include <cuda_fp16.h>
#include <cstdint>

#define BATCH 8
#define HW    2304        // 48*48
#define CH    256
#define K2    512         // AhT layout: [hi(256) | lo(256)]
#define KH    256         // Ah/Bh hi-only row stride
#define GSLICES 6
#define GK     (HW / GSLICES)   // 384

// ---------------- scratch (device globals: allocation-free rule) -----------
__device__ float g_Gpart[GSLICES][BATCH][CH][CH];   // 12 MB (tile (1,0) unused)
__device__ float g_Qpart[BATCH][2][HW];             // 147 KB
__device__ __half g_Ah[(size_t)BATCH * HW * KH];    // 9.4 MB (hi only)
__device__ __half g_Bh[(size_t)BATCH * HW * KH];    // 9.4 MB (hi only)
__device__ __half g_AhT[(size_t)BATCH * K2 * HW];   // 18.9 MB  [c(hi|lo)][m]
__device__ __half g_Gh[(size_t)BATCH * CH * CH];    // 1 MB (hi only)

__device__ __forceinline__ uint32_t smem_u32(const void* p) {
    return (uint32_t)__cvta_generic_to_shared((void*)p);
}
__device__ __forceinline__ uint32_t sw128(uint32_t off) {
    return off ^ ((off >> 3) & 0x70);
}

__device__ __forceinline__ void ldsm_x4(uint32_t* r, uint32_t addr) {
    asm volatile("ldmatrix.sync.aligned.m8n8.x4.shared.b16 {%0,%1,%2,%3}, [%4];"
                 : "=r"(r[0]), "=r"(r[1]), "=r"(r[2]), "=r"(r[3]) : "r"(addr));
}
__device__ __forceinline__ void mma16816(float* c, const uint32_t* a,
                                         uint32_t b0, uint32_t b1) {
    asm volatile("mma.sync.aligned.m16n8k16.row.col.f32.f16.f16.f32 "
                 "{%0,%1,%2,%3}, {%4,%5,%6,%7}, {%8,%9}, {%0,%1,%2,%3};"
                 : "+f"(c[0]), "+f"(c[1]), "+f"(c[2]), "+f"(c[3])
                 : "r"(a[0]), "r"(a[1]), "r"(a[2]), "r"(a[3]), "r"(b0), "r"(b1));
}
__device__ __forceinline__ void cp_async16(uint32_t dst, const void* src) {
    asm volatile("cp.async.cg.shared.global [%0], [%1], 16;" :: "r"(dst), "l"(src));
}
__device__ __forceinline__ void cp_commit() {
    asm volatile("cp.async.commit_group;" ::: "memory");
}
template <int N> __device__ __forceinline__ void cp_wait() {
    asm volatile("cp.async.wait_group %0;" :: "n"(N) : "memory");
}

// ---- shared 128x128-tile GEMM pieces (8 warps, 4x2) -----------------------
#define CHUNK_BYTES 16384
#define BUF_BYTES   (2 * CHUNK_BYTES)
#define NSTAGE      3
#define SMEM_BUFS   (NSTAGE * BUF_BYTES)    // 98304
#define SMEM_AUX    (SMEM_BUFS + 1024)      // + dedicated sSc/qs slot

__device__ __forceinline__ void mma_chunk(uint32_t aBase, uint32_t bBase,
                                          int wm, int wn, int lane,
                                          float acc[2][8][4])
{
    const int i8 = lane & 7;
    const int g  = lane >> 3;
    #pragma unroll
    for (int ks = 0; ks < 4; ++ks) {
        const int kb = ks * 32;
        uint32_t afr[2][4];
        #pragma unroll
        for (int mi = 0; mi < 2; ++mi) {
            int row = wm + mi * 16 + i8 + (g & 1) * 8;
            int col = kb + (g >> 1) * 16;
            ldsm_x4(afr[mi], aBase + sw128((uint32_t)(row * 128 + col)));
        }
        uint32_t bfr[4][4];
        #pragma unroll
        for (int p = 0; p < 4; ++p) {
            int row = wn + p * 16 + i8 + (g >> 1) * 8;
            int col = kb + (g & 1) * 16;
            ldsm_x4(bfr[p], bBase + sw128((uint32_t)(row * 128 + col)));
        }
        #pragma unroll
        for (int mi = 0; mi < 2; ++mi)
            #pragma unroll
            for (int nj = 0; nj < 8; ++nj)
                mma16816(acc[mi][nj], afr[mi],
                         bfr[nj >> 1][(nj & 1) * 2],
                         bfr[nj >> 1][(nj & 1) * 2 + 1]);
    }
}

// ---------------------------------------------------------------------------
// convertAB: vectorized one pass, 32m x 64c blocks.
// ---------------------------------------------------------------------------
__global__ __launch_bounds__(256) void convertAB_kernel(const float* __restrict__ Ax,
                                                        const float* __restrict__ Bx)
{
    __shared__ float T[32][65];
    const int b   = blockIdx.z;
    const int m0  = blockIdx.x * 32;
    const int c0  = blockIdx.y * 64;
    const int tid = threadIdx.x;
    const int tx  = tid & 31;
    const int w   = tid >> 5;

    __half* Br = g_Bh + (size_t)b * HW * KH;
    __half* Ar = g_Ah + (size_t)b * HW * KH;
    #pragma unroll
    for (int k = 0; k < 4; ++k) {
        int m = w + k * 8;
        size_t grow = ((size_t)b * HW + m0 + m) * CH + c0 + tx * 2;
        float2 bv = *(const float2*)&Bx[grow];
        *(__half2*)&Br[(size_t)(m0 + m) * KH + c0 + tx * 2] =
            __halves2half2(__float2half(bv.x), __float2half(bv.y));
        float2 av = *(const float2*)&Ax[grow];
        T[m][tx * 2]     = av.x;
        T[m][tx * 2 + 1] = av.y;
        *(__half2*)&Ar[(size_t)(m0 + m) * KH + c0 + tx * 2] =
            __halves2half2(__float2half(av.x), __float2half(av.y));
    }
    __syncthreads();

    __half* At = g_AhT + (size_t)b * K2 * HW;
    const int p  = tid & 15;
    const int cb = tid >> 4;
    #pragma unroll
    for (int j = 0; j < 4; ++j) {
        int c = cb + 16 * j;
        float v0 = T[p * 2][c], v1 = T[p * 2 + 1][c];
        __half h0 = __float2half(v0), h1 = __float2half(v1);
        __half l0 = __float2half(v0 - __half2float(h0));
        __half l1 = __float2half(v1 - __half2float(h1));
        *(__half2*)&At[(size_t)(c0 + c) * HW + m0 + p * 2]      = __halves2half2(h0, h1);
        *(__half2*)&At[(size_t)(c0 + c + CH) * HW + m0 + p * 2] = __halves2half2(l0, l1);
    }
}

// ---------------------------------------------------------------------------
// gram_mma: symmetric — tiles (0,0),(1,1),(0,1). 2-term fp16 (12 chunk iters).
// ---------------------------------------------------------------------------
__global__ __launch_bounds__(256, 2) void gram_mma_kernel()
{
    extern __shared__ char smem[];
    const uint32_t smem_base = smem_u32(smem);
    const int tid  = threadIdx.x;
    const int wid  = tid >> 5;
    const int lane = tid & 31;

    const int b     = blockIdx.z / GSLICES;
    const int slice = blockIdx.z % GSLICES;
    const int t     = blockIdx.x;                 // 0:(0,0) 1:(128,128) 2:(0,128)
    const int c1_0  = (t == 1) ? 128 : 0;
    const int c2_0  = (t == 0) ? 0 : 128;

    const __half* At = g_AhT + (size_t)b * K2 * HW;

    uint32_t dstoff[8];
    const __half* srcp[8];
    bool isA[8];
    #pragma unroll
    for (int it = 0; it < 8; ++it) {
        int idx = it * 256 + tid;
        int li  = idx & 1023;
        int row = li >> 3;
        int seg = li & 7;
        isA[it] = (idx < 1024);
        dstoff[it] = (isA[it] ? 0u : (uint32_t)CHUNK_BYTES)
                   + sw128((uint32_t)(row * 128 + seg * 16));
        srcp[it] = At + (size_t)((isA[it] ? c1_0 : c2_0) + row) * HW + seg * 8;
    }

    const int NIT = 12;
    auto load_chunk = [&](int it, int buf) {
        const int term = it / 6, kc = it - term * 6;
        const size_t aoff = (size_t)(term == 1 ? CH : 0) * HW + slice * GK + kc * 64;
        const size_t boff = (size_t)(slice * GK + kc * 64);
        const uint32_t base = smem_base + buf * BUF_BYTES;
        #pragma unroll
        for (int s = 0; s < 8; ++s)
            cp_async16(base + dstoff[s], srcp[s] + (isA[s] ? aoff : boff));
        cp_commit();
    };

    const int wm = (wid & 3) * 32;
    const int wn = (wid >> 2) * 64;
    float acc[2][8][4] = {};

    load_chunk(0, 0);
    load_chunk(1, 1);
    for (int c = 0; c < NIT; ++c) {
        if (c < NIT - 1) cp_wait<1>(); else cp_wait<0>();
        __syncthreads();
        const uint32_t aBase = smem_base + (c % NSTAGE) * BUF_BYTES;
        mma_chunk(aBase, aBase + CHUNK_BYTES, wm, wn, lane, acc);
        if (c + 2 < NIT) load_chunk(c + 2, (c + 2) % NSTAGE);
    }

    const int r    = lane >> 2;
    const int cpos = (lane & 3) * 2;
    #pragma unroll
    for (int mi = 0; mi < 2; ++mi) {
        const int row = c1_0 + wm + mi * 16 + r;
        float* o0 = &g_Gpart[slice][b][row][c2_0 + wn];
        float* o1 = o0 + 8 * CH;
        #pragma unroll
        for (int nj = 0; nj < 8; ++nj) {
            *(float2*)&o0[nj * 8 + cpos] = make_float2(acc[mi][nj][0], acc[mi][nj][1]);
            *(float2*)&o1[nj * 8 + cpos] = make_float2(acc[mi][nj][2], acc[mi][nj][3]);
        }
    }
}

// ---------------------------------------------------------------------------
// greduce: float4-vectorized; write fp16 hi; mirror (1,0).
// ---------------------------------------------------------------------------
__global__ __launch_bounds__(256) void greduce_kernel()
{
    const int per_b = 3 * 128 * 32;
    const int total = BATCH * per_b;
    const int full  = BATCH * CH * CH;
    const float* p = &g_Gpart[0][0][0][0];
    for (int i = blockIdx.x * blockDim.x + threadIdx.x; i < total;
         i += gridDim.x * blockDim.x) {
        int b   = i / per_b;
        int rem = i - b * per_b;
        int t   = rem >> 12;
        int r2  = rem & 4095;
        int r   = r2 >> 5;
        int cc  = (r2 & 31) * 4;
        int c   = ((t == 1) ? 128 : 0) + r;
        int c2  = ((t == 0) ? 0 : 128) + cc;

        size_t off = (size_t)b * CH * CH + (size_t)c * CH + c2;
        float4 s = make_float4(0.f, 0.f, 0.f, 0.f);
        #pragma unroll
        for (int k = 0; k < GSLICES; ++k) {
            float4 v = *(const float4*)&p[(size_t)k * full + off];
            s.x += v.x; s.y += v.y; s.z += v.z; s.w += v.w;
        }
        __half h0 = __float2half(s.x), h1 = __float2half(s.y);
        __half h2 = __float2half(s.z), h3 = __float2half(s.w);
        *(__half2*)&g_Gh[((size_t)b * CH + c) * CH + c2]     = __halves2half2(h0, h1);
        *(__half2*)&g_Gh[((size_t)b * CH + c) * CH + c2 + 2] = __halves2half2(h2, h3);
        if (t == 2) {
            g_Gh[((size_t)b * CH + c2 + 0) * CH + c] = h0;
            g_Gh[((size_t)b * CH + c2 + 1) * CH + c] = h1;
            g_Gh[((size_t)b * CH + c2 + 2) * CH + c] = h2;
            g_Gh[((size_t)b * CH + c2 + 3) * CH + c] = h3;
        }
    }
}

// ---------------------------------------------------------------------------
// qrow_mma: V = Uhi Ghi (1-term fp16, 4 chunks).
// Epilogue q_part = rowsum(V .* Uhi) — Uhi read as half2 from g_Bh (L2-hot).
// ---------------------------------------------------------------------------
__global__ __launch_bounds__(256, 2) void qrow_mma_kernel()
{
    extern __shared__ char smem[];
    const uint32_t smem_base = smem_u32(smem);
    const int tid  = threadIdx.x;
    const int wid  = tid >> 5;
    const int lane = tid & 31;

    const int ctile = blockIdx.x;
    const int n0    = blockIdx.y * 128;
    const int b     = blockIdx.z;

    const __half* Ub = g_Bh + ((size_t)b * HW + n0) * KH;
    const __half* Gb = g_Gh + (size_t)b * CH * CH + (size_t)ctile * 128 * CH;

    uint32_t dstoff[8];
    const __half* srcp[8];
    #pragma unroll
    for (int it = 0; it < 8; ++it) {
        int idx = it * 256 + tid;
        int li  = idx & 1023;
        int row = li >> 3;
        int seg = li & 7;
        bool isA = (idx < 1024);
        dstoff[it] = (isA ? 0u : (uint32_t)CHUNK_BYTES)
                   + sw128((uint32_t)(row * 128 + seg * 16));
        srcp[it] = (isA ? Ub + (size_t)row * KH : Gb + (size_t)row * CH) + seg * 8;
    }

    const int NIT = 4;
    auto load_chunk = [&](int it, int buf) {
        const size_t off = (size_t)it * 64;
        const uint32_t base = smem_base + buf * BUF_BYTES;
        #pragma unroll
        for (int s = 0; s < 8; ++s)
            cp_async16(base + dstoff[s], srcp[s] + off);
        cp_commit();
    };

    const int wm = (wid & 3) * 32;
    const int wn = (wid >> 2) * 64;
    float acc[2][8][4] = {};

    load_chunk(0, 0);
    load_chunk(1, 1);
    for (int c = 0; c < NIT; ++c) {
        if (c < NIT - 1) cp_wait<1>(); else cp_wait<0>();
        __syncthreads();
        const uint32_t aBase = smem_base + (c % NSTAGE) * BUF_BYTES;
        mma_chunk(aBase, aBase + CHUNK_BYTES, wm, wn, lane, acc);
        if (c + 2 < NIT) load_chunk(c + 2, (c + 2) % NSTAGE);
    }

    // qs lives in the dedicated slot past the buffers — no extra sync needed
    float* qs = (float*)(smem + SMEM_BUFS);
    const int r    = lane >> 2;
    const int cpos = (lane & 3) * 2;

    float rs[2][2] = {};
    #pragma unroll
    for (int mi = 0; mi < 2; ++mi) {
        const size_t row0 = (size_t)b * HW + n0 + wm + mi * 16 + r;
        #pragma unroll
        for (int nj = 0; nj < 8; ++nj) {
            const int cc = ctile * 128 + wn + nj * 8 + cpos;
            __half2 uh0 = *(const __half2*)&g_Bh[row0 * KH + cc];
            __half2 uh1 = *(const __half2*)&g_Bh[(row0 + 8) * KH + cc];
            float2 u0 = __half22float2(uh0);
            float2 u1 = __half22float2(uh1);
            rs[mi][0] += acc[mi][nj][0] * u0.x + acc[mi][nj][1] * u0.y;
            rs[mi][1] += acc[mi][nj][2] * u1.x + acc[mi][nj][3] * u1.y;
        }
    }
    #pragma unroll
    for (int mi = 0; mi < 2; ++mi)
        #pragma unroll
        for (int h = 0; h < 2; ++h) {
            float v = rs[mi][h];
            v += __shfl_xor_sync(0xffffffffu, v, 1);
            v += __shfl_xor_sync(0xffffffffu, v, 2);
            rs[mi][h] = v;
        }
    if ((lane & 3) == 0) {
        #pragma unroll
        for (int mi = 0; mi < 2; ++mi)
            #pragma unroll
            for (int h = 0; h < 2; ++h)
                qs[(wid >> 2) * 128 + wm + mi * 16 + r + h * 8] = rs[mi][h];
    }
    __syncthreads();
    if (tid < 128)
        g_Qpart[b][ctile][n0 + tid] = qs[tid] + qs[128 + tid];
}

// ---------------------------------------------------------------------------
// corr_mma: 128x128 CTA tile, 8 warps (4x2), 3-stage pipeline.
// 1-term fp16. sSc written to dedicated smem slot at kernel start.
// ---------------------------------------------------------------------------
#define NCHUNK 4
__global__ __launch_bounds__(256, 2) void corr_mma_kernel(float* __restrict__ out)
{
    extern __shared__ char smem[];
    const uint32_t smem_base = smem_u32(smem);
    const int tid  = threadIdx.x;
    const int wid  = tid >> 5;
    const int lane = tid & 31;

    const int b  = blockIdx.z;
    const int m0 = blockIdx.y * 128;
    const int n0 = blockIdx.x * 128;

    // scale straight into the dedicated smem slot; mainloop syncs cover visibility
    float* sSc = (float*)(smem + SMEM_BUFS);
    if (tid < 128)
        sSc[tid] = rsqrtf(g_Qpart[b][0][n0 + tid] + g_Qpart[b][1][n0 + tid]);

    const __half* Ab = g_Ah + ((size_t)b * HW + m0) * KH;
    const __half* Bb = g_Bh + ((size_t)b * HW + n0) * KH;

    uint32_t dstoff[8];
    const __half* srcp[8];
    #pragma unroll
    for (int it = 0; it < 8; ++it) {
        int idx = it * 256 + tid;
        int li  = idx & 1023;
        int row = li >> 3;
        int seg = li & 7;
        bool isA = (idx < 1024);
        dstoff[it] = (isA ? 0u : (uint32_t)CHUNK_BYTES)
                   + sw128((uint32_t)(row * 128 + seg * 16));
        srcp[it] = (isA ? Ab : Bb) + (size_t)row * KH + seg * 8;
    }

    auto load_chunk = [&](int c, int buf) {
        const uint32_t base = smem_base + buf * BUF_BYTES;
        const int ko = c * 64;
        #pragma unroll
        for (int it = 0; it < 8; ++it)
            cp_async16(base + dstoff[it], srcp[it] + ko);
        cp_commit();
    };

    const int wm = (wid & 3) * 32;
    const int wn = (wid >> 2) * 64;
    float acc[2][8][4] = {};

    load_chunk(0, 0);
    load_chunk(1, 1);
    for (int c = 0; c < NCHUNK; ++c) {
        if (c < NCHUNK - 1) cp_wait<1>(); else cp_wait<0>();
        __syncthreads();
        const uint32_t aBase = smem_base + (c % NSTAGE) * BUF_BYTES;
        mma_chunk(aBase, aBase + CHUNK_BYTES, wm, wn, lane, acc);
        if (c + 2 < NCHUNK) load_chunk(c + 2, (c + 2) % NSTAGE);
    }
    __syncthreads();   // mainloop done; sSc visible (written pre-loop)

    const int r    = lane >> 2;
    const int cpos = (lane & 3) * 2;
    #pragma unroll
    for (int mi = 0; mi < 2; ++mi) {
        const int mrow = m0 + wm + mi * 16 + r;
        float* o0 = out + ((size_t)b * HW + mrow) * HW + n0 + wn;
        float* o1 = o0 + (size_t)8 * HW;
        #pragma unroll
        for (int nj = 0; nj < 8; ++nj) {
            const int nc = wn + nj * 8 + cpos;
            const float s0 = sSc[nc], s1 = sSc[nc + 1];
            float2 v0 = make_float2(acc[mi][nj][0] * s0, acc[mi][nj][1] * s1);
            float2 v1 = make_float2(acc[mi][nj][2] * s0, acc[mi][nj][3] * s1);
            *(float2*)&o0[nj * 8 + cpos] = v0;
            *(float2*)&o1[nj * 8 + cpos] = v1;
        }
    }
}

// ---------------------------------------------------------------------------
extern "C" void kernel_launch(void* const* d_in, const int* in_sizes, int n_in,
                              void* d_out, int out_size)
{
    const float* A = (const float*)d_in[0];
    const float* B = (const float*)d_in[1];
    float* out = (float*)d_out;

    static bool init = false;
    if (!init) {
        init = true;
        cudaFuncSetAttribute(corr_mma_kernel,
                             cudaFuncAttributeMaxDynamicSharedMemorySize, SMEM_AUX);
        cudaFuncSetAttribute(gram_mma_kernel,
                             cudaFuncAttributeMaxDynamicSharedMemorySize, SMEM_AUX);
        cudaFuncSetAttribute(qrow_mma_kernel,
                             cudaFuncAttributeMaxDynamicSharedMemorySize, SMEM_AUX);
    }

    convertAB_kernel<<<dim3(HW / 32, CH / 64, BATCH), 256>>>(A, B);
    gram_mma_kernel<<<dim3(3, 1, BATCH * GSLICES), 256, SMEM_AUX>>>();
    greduce_kernel<<<384, 256>>>();
    qrow_mma_kernel<<<dim3(2, HW / 128, BATCH), 256, SMEM_AUX>>>();
    corr_mma_kernel<<<dim3(HW / 128, HW / 128, BATCH), 256, SMEM_AUX>>>(out);
}

// round 17
// speedup vs baseline: 1.0155x; 1.0155x over previous
#include <cuda_runtime.h>
#include <cuda_fp16.h>
#include <cstdint>

#define BATCH 8
#define HW    2304        // 48*48
#define CH    256
#define K2    512         // AhT layout: [hi(256) | lo(256)]
#define KH    256         // Ah/Bh hi-only row stride
#define GSLICES 6
#define GK     (HW / GSLICES)   // 384

// ---------------- scratch (device globals: allocation-free rule) -----------
__device__ float g_Gpart[GSLICES][BATCH][CH][CH];   // 12 MB (tile (1,0) unused)
__device__ float g_Qpart[BATCH][2][HW];             // 147 KB
__device__ __half g_Ah[(size_t)BATCH * HW * KH];    // 9.4 MB (hi only)
__device__ __half g_Bh[(size_t)BATCH * HW * KH];    // 9.4 MB (hi only)
__device__ __half g_AhT[(size_t)BATCH * K2 * HW];   // 18.9 MB  [c(hi|lo)][m]
__device__ __half g_Gh[(size_t)BATCH * CH * CH];    // 1 MB (hi only)

__device__ __forceinline__ uint32_t smem_u32(const void* p) {
    return (uint32_t)__cvta_generic_to_shared((void*)p);
}
__device__ __forceinline__ uint32_t sw128(uint32_t off) {
    return off ^ ((off >> 3) & 0x70);
}

__device__ __forceinline__ void ldsm_x4(uint32_t* r, uint32_t addr) {
    asm volatile("ldmatrix.sync.aligned.m8n8.x4.shared.b16 {%0,%1,%2,%3}, [%4];"
                 : "=r"(r[0]), "=r"(r[1]), "=r"(r[2]), "=r"(r[3]) : "r"(addr));
}
__device__ __forceinline__ void mma16816(float* c, const uint32_t* a,
                                         uint32_t b0, uint32_t b1) {
    asm volatile("mma.sync.aligned.m16n8k16.row.col.f32.f16.f16.f32 "
                 "{%0,%1,%2,%3}, {%4,%5,%6,%7}, {%8,%9}, {%0,%1,%2,%3};"
                 : "+f"(c[0]), "+f"(c[1]), "+f"(c[2]), "+f"(c[3])
                 : "r"(a[0]), "r"(a[1]), "r"(a[2]), "r"(a[3]), "r"(b0), "r"(b1));
}
__device__ __forceinline__ void cp_async16(uint32_t dst, const void* src) {
    asm volatile("cp.async.cg.shared.global [%0], [%1], 16;" :: "r"(dst), "l"(src));
}
__device__ __forceinline__ void cp_commit() {
    asm volatile("cp.async.commit_group;" ::: "memory");
}
template <int N> __device__ __forceinline__ void cp_wait() {
    asm volatile("cp.async.wait_group %0;" :: "n"(N) : "memory");
}

// ---- shared 128x128-tile GEMM pieces (8 warps, 4x2) -----------------------
#define CHUNK_BYTES 16384
#define BUF_BYTES   (2 * CHUNK_BYTES)
#define NSTAGE      3
#define SMEM_BUFS   (NSTAGE * BUF_BYTES)    // 98304
#define SMEM_AUX    (SMEM_BUFS + 1024)      // + dedicated qs slot

__device__ __forceinline__ void mma_chunk(uint32_t aBase, uint32_t bBase,
                                          int wm, int wn, int lane,
                                          float acc[2][8][4])
{
    const int i8 = lane & 7;
    const int g  = lane >> 3;
    #pragma unroll
    for (int ks = 0; ks < 4; ++ks) {
        const int kb = ks * 32;
        uint32_t afr[2][4];
        #pragma unroll
        for (int mi = 0; mi < 2; ++mi) {
            int row = wm + mi * 16 + i8 + (g & 1) * 8;
            int col = kb + (g >> 1) * 16;
            ldsm_x4(afr[mi], aBase + sw128((uint32_t)(row * 128 + col)));
        }
        uint32_t bfr[4][4];
        #pragma unroll
        for (int p = 0; p < 4; ++p) {
            int row = wn + p * 16 + i8 + (g >> 1) * 8;
            int col = kb + (g & 1) * 16;
            ldsm_x4(bfr[p], bBase + sw128((uint32_t)(row * 128 + col)));
        }
        #pragma unroll
        for (int mi = 0; mi < 2; ++mi)
            #pragma unroll
            for (int nj = 0; nj < 8; ++nj)
                mma16816(acc[mi][nj], afr[mi],
                         bfr[nj >> 1][(nj & 1) * 2],
                         bfr[nj >> 1][(nj & 1) * 2 + 1]);
    }
}

// ---------------------------------------------------------------------------
// convertAB: vectorized one pass, 32m x 64c blocks.
// ---------------------------------------------------------------------------
__global__ __launch_bounds__(256) void convertAB_kernel(const float* __restrict__ Ax,
                                                        const float* __restrict__ Bx)
{
    __shared__ float T[32][65];
    const int b   = blockIdx.z;
    const int m0  = blockIdx.x * 32;
    const int c0  = blockIdx.y * 64;
    const int tid = threadIdx.x;
    const int tx  = tid & 31;
    const int w   = tid >> 5;

    __half* Br = g_Bh + (size_t)b * HW * KH;
    __half* Ar = g_Ah + (size_t)b * HW * KH;
    #pragma unroll
    for (int k = 0; k < 4; ++k) {
        int m = w + k * 8;
        size_t grow = ((size_t)b * HW + m0 + m) * CH + c0 + tx * 2;
        float2 bv = *(const float2*)&Bx[grow];
        *(__half2*)&Br[(size_t)(m0 + m) * KH + c0 + tx * 2] =
            __halves2half2(__float2half(bv.x), __float2half(bv.y));
        float2 av = *(const float2*)&Ax[grow];
        T[m][tx * 2]     = av.x;
        T[m][tx * 2 + 1] = av.y;
        *(__half2*)&Ar[(size_t)(m0 + m) * KH + c0 + tx * 2] =
            __halves2half2(__float2half(av.x), __float2half(av.y));
    }
    __syncthreads();

    __half* At = g_AhT + (size_t)b * K2 * HW;
    const int p  = tid & 15;
    const int cb = tid >> 4;
    #pragma unroll
    for (int j = 0; j < 4; ++j) {
        int c = cb + 16 * j;
        float v0 = T[p * 2][c], v1 = T[p * 2 + 1][c];
        __half h0 = __float2half(v0), h1 = __float2half(v1);
        __half l0 = __float2half(v0 - __half2float(h0));
        __half l1 = __float2half(v1 - __half2float(h1));
        *(__half2*)&At[(size_t)(c0 + c) * HW + m0 + p * 2]      = __halves2half2(h0, h1);
        *(__half2*)&At[(size_t)(c0 + c + CH) * HW + m0 + p * 2] = __halves2half2(l0, l1);
    }
}

// ---------------------------------------------------------------------------
// gram_mma: symmetric — tiles (0,0),(1,1),(0,1). 2-term fp16 (12 chunk iters).
// ---------------------------------------------------------------------------
__global__ __launch_bounds__(256, 2) void gram_mma_kernel()
{
    extern __shared__ char smem[];
    const uint32_t smem_base = smem_u32(smem);
    const int tid  = threadIdx.x;
    const int wid  = tid >> 5;
    const int lane = tid & 31;

    const int b     = blockIdx.z / GSLICES;
    const int slice = blockIdx.z % GSLICES;
    const int t     = blockIdx.x;                 // 0:(0,0) 1:(128,128) 2:(0,128)
    const int c1_0  = (t == 1) ? 128 : 0;
    const int c2_0  = (t == 0) ? 0 : 128;

    const __half* At = g_AhT + (size_t)b * K2 * HW;

    uint32_t dstoff[8];
    const __half* srcp[8];
    bool isA[8];
    #pragma unroll
    for (int it = 0; it < 8; ++it) {
        int idx = it * 256 + tid;
        int li  = idx & 1023;
        int row = li >> 3;
        int seg = li & 7;
        isA[it] = (idx < 1024);
        dstoff[it] = (isA[it] ? 0u : (uint32_t)CHUNK_BYTES)
                   + sw128((uint32_t)(row * 128 + seg * 16));
        srcp[it] = At + (size_t)((isA[it] ? c1_0 : c2_0) + row) * HW + seg * 8;
    }

    const int NIT = 12;
    auto load_chunk = [&](int it, int buf) {
        const int term = it / 6, kc = it - term * 6;
        const size_t aoff = (size_t)(term == 1 ? CH : 0) * HW + slice * GK + kc * 64;
        const size_t boff = (size_t)(slice * GK + kc * 64);
        const uint32_t base = smem_base + buf * BUF_BYTES;
        #pragma unroll
        for (int s = 0; s < 8; ++s)
            cp_async16(base + dstoff[s], srcp[s] + (isA[s] ? aoff : boff));
        cp_commit();
    };

    const int wm = (wid & 3) * 32;
    const int wn = (wid >> 2) * 64;
    float acc[2][8][4] = {};

    load_chunk(0, 0);
    load_chunk(1, 1);
    for (int c = 0; c < NIT; ++c) {
        if (c < NIT - 1) cp_wait<1>(); else cp_wait<0>();
        __syncthreads();
        const uint32_t aBase = smem_base + (c % NSTAGE) * BUF_BYTES;
        mma_chunk(aBase, aBase + CHUNK_BYTES, wm, wn, lane, acc);
        if (c + 2 < NIT) load_chunk(c + 2, (c + 2) % NSTAGE);
    }

    const int r    = lane >> 2;
    const int cpos = (lane & 3) * 2;
    #pragma unroll
    for (int mi = 0; mi < 2; ++mi) {
        const int row = c1_0 + wm + mi * 16 + r;
        float* o0 = &g_Gpart[slice][b][row][c2_0 + wn];
        float* o1 = o0 + 8 * CH;
        #pragma unroll
        for (int nj = 0; nj < 8; ++nj) {
            *(float2*)&o0[nj * 8 + cpos] = make_float2(acc[mi][nj][0], acc[mi][nj][1]);
            *(float2*)&o1[nj * 8 + cpos] = make_float2(acc[mi][nj][2], acc[mi][nj][3]);
        }
    }
}

// ---------------------------------------------------------------------------
// greduce: float4-vectorized; write fp16 hi; mirror (1,0).
// ---------------------------------------------------------------------------
__global__ __launch_bounds__(256) void greduce_kernel()
{
    const int per_b = 3 * 128 * 32;
    const int total = BATCH * per_b;
    const int full  = BATCH * CH * CH;
    const float* p = &g_Gpart[0][0][0][0];
    for (int i = blockIdx.x * blockDim.x + threadIdx.x; i < total;
         i += gridDim.x * blockDim.x) {
        int b   = i / per_b;
        int rem = i - b * per_b;
        int t   = rem >> 12;
        int r2  = rem & 4095;
        int r   = r2 >> 5;
        int cc  = (r2 & 31) * 4;
        int c   = ((t == 1) ? 128 : 0) + r;
        int c2  = ((t == 0) ? 0 : 128) + cc;

        size_t off = (size_t)b * CH * CH + (size_t)c * CH + c2;
        float4 s = make_float4(0.f, 0.f, 0.f, 0.f);
        #pragma unroll
        for (int k = 0; k < GSLICES; ++k) {
            float4 v = *(const float4*)&p[(size_t)k * full + off];
            s.x += v.x; s.y += v.y; s.z += v.z; s.w += v.w;
        }
        __half h0 = __float2half(s.x), h1 = __float2half(s.y);
        __half h2 = __float2half(s.z), h3 = __float2half(s.w);
        *(__half2*)&g_Gh[((size_t)b * CH + c) * CH + c2]     = __halves2half2(h0, h1);
        *(__half2*)&g_Gh[((size_t)b * CH + c) * CH + c2 + 2] = __halves2half2(h2, h3);
        if (t == 2) {
            g_Gh[((size_t)b * CH + c2 + 0) * CH + c] = h0;
            g_Gh[((size_t)b * CH + c2 + 1) * CH + c] = h1;
            g_Gh[((size_t)b * CH + c2 + 2) * CH + c] = h2;
            g_Gh[((size_t)b * CH + c2 + 3) * CH + c] = h3;
        }
    }
}

// ---------------------------------------------------------------------------
// qrow_mma: V = Uhi Ghi (1-term fp16, 4 chunks).
// Epilogue q_part = rowsum(V .* Uhi) — Uhi read as half2 from g_Bh (L2-hot).
// ---------------------------------------------------------------------------
__global__ __launch_bounds__(256, 2) void qrow_mma_kernel()
{
    extern __shared__ char smem[];
    const uint32_t smem_base = smem_u32(smem);
    const int tid  = threadIdx.x;
    const int wid  = tid >> 5;
    const int lane = tid & 31;

    const int ctile = blockIdx.x;
    const int n0    = blockIdx.y * 128;
    const int b     = blockIdx.z;

    const __half* Ub = g_Bh + ((size_t)b * HW + n0) * KH;
    const __half* Gb = g_Gh + (size_t)b * CH * CH + (size_t)ctile * 128 * CH;

    uint32_t dstoff[8];
    const __half* srcp[8];
    #pragma unroll
    for (int it = 0; it < 8; ++it) {
        int idx = it * 256 + tid;
        int li  = idx & 1023;
        int row = li >> 3;
        int seg = li & 7;
        bool isA = (idx < 1024);
        dstoff[it] = (isA ? 0u : (uint32_t)CHUNK_BYTES)
                   + sw128((uint32_t)(row * 128 + seg * 16));
        srcp[it] = (isA ? Ub + (size_t)row * KH : Gb + (size_t)row * CH) + seg * 8;
    }

    const int NIT = 4;
    auto load_chunk = [&](int it, int buf) {
        const size_t off = (size_t)it * 64;
        const uint32_t base = smem_base + buf * BUF_BYTES;
        #pragma unroll
        for (int s = 0; s < 8; ++s)
            cp_async16(base + dstoff[s], srcp[s] + off);
        cp_commit();
    };

    const int wm = (wid & 3) * 32;
    const int wn = (wid >> 2) * 64;
    float acc[2][8][4] = {};

    load_chunk(0, 0);
    load_chunk(1, 1);
    for (int c = 0; c < NIT; ++c) {
        if (c < NIT - 1) cp_wait<1>(); else cp_wait<0>();
        __syncthreads();
        const uint32_t aBase = smem_base + (c % NSTAGE) * BUF_BYTES;
        mma_chunk(aBase, aBase + CHUNK_BYTES, wm, wn, lane, acc);
        if (c + 2 < NIT) load_chunk(c + 2, (c + 2) % NSTAGE);
    }

    // qs lives in the dedicated slot past the buffers — no extra sync needed
    float* qs = (float*)(smem + SMEM_BUFS);
    const int r    = lane >> 2;
    const int cpos = (lane & 3) * 2;

    float rs[2][2] = {};
    #pragma unroll
    for (int mi = 0; mi < 2; ++mi) {
        const size_t row0 = (size_t)b * HW + n0 + wm + mi * 16 + r;
        #pragma unroll
        for (int nj = 0; nj < 8; ++nj) {
            const int cc = ctile * 128 + wn + nj * 8 + cpos;
            __half2 uh0 = *(const __half2*)&g_Bh[row0 * KH + cc];
            __half2 uh1 = *(const __half2*)&g_Bh[(row0 + 8) * KH + cc];
            float2 u0 = __half22float2(uh0);
            float2 u1 = __half22float2(uh1);
            rs[mi][0] += acc[mi][nj][0] * u0.x + acc[mi][nj][1] * u0.y;
            rs[mi][1] += acc[mi][nj][2] * u1.x + acc[mi][nj][3] * u1.y;
        }
    }
    #pragma unroll
    for (int mi = 0; mi < 2; ++mi)
        #pragma unroll
        for (int h = 0; h < 2; ++h) {
            float v = rs[mi][h];
            v += __shfl_xor_sync(0xffffffffu, v, 1);
            v += __shfl_xor_sync(0xffffffffu, v, 2);
            rs[mi][h] = v;
        }
    if ((lane & 3) == 0) {
        #pragma unroll
        for (int mi = 0; mi < 2; ++mi)
            #pragma unroll
            for (int h = 0; h < 2; ++h)
                qs[(wid >> 2) * 128 + wm + mi * 16 + r + h * 8] = rs[mi][h];
    }
    __syncthreads();
    if (tid < 128)
        g_Qpart[b][ctile][n0 + tid] = qs[tid] + qs[128 + tid];
}

// ---------------------------------------------------------------------------
// corr_mma: 128x128 CTA tile, 8 warps (4x2), 3-stage pipeline.
// 1-term fp16: 4 K-chunks (hi . hi). Register-prefetched rsqrt-scale epilogue
// (R14-measured-best shape: prefetch into reg, stage to smem after mainloop).
// ---------------------------------------------------------------------------
#define NCHUNK 4
__global__ __launch_bounds__(256, 2) void corr_mma_kernel(float* __restrict__ out)
{
    extern __shared__ char smem[];
    const uint32_t smem_base = smem_u32(smem);
    const int tid  = threadIdx.x;
    const int wid  = tid >> 5;
    const int lane = tid & 31;

    const int b  = blockIdx.z;
    const int m0 = blockIdx.y * 128;
    const int n0 = blockIdx.x * 128;

    // prefetch scale early (latency hidden behind the mainloop)
    float spre = 0.f;
    if (tid < 128)
        spre = rsqrtf(g_Qpart[b][0][n0 + tid] + g_Qpart[b][1][n0 + tid]);

    const __half* Ab = g_Ah + ((size_t)b * HW + m0) * KH;
    const __half* Bb = g_Bh + ((size_t)b * HW + n0) * KH;

    uint32_t dstoff[8];
    const __half* srcp[8];
    #pragma unroll
    for (int it = 0; it < 8; ++it) {
        int idx = it * 256 + tid;
        int li  = idx & 1023;
        int row = li >> 3;
        int seg = li & 7;
        bool isA = (idx < 1024);
        dstoff[it] = (isA ? 0u : (uint32_t)CHUNK_BYTES)
                   + sw128((uint32_t)(row * 128 + seg * 16));
        srcp[it] = (isA ? Ab : Bb) + (size_t)row * KH + seg * 8;
    }

    auto load_chunk = [&](int c, int buf) {
        const uint32_t base = smem_base + buf * BUF_BYTES;
        const int ko = c * 64;
        #pragma unroll
        for (int it = 0; it < 8; ++it)
            cp_async16(base + dstoff[it], srcp[it] + ko);
        cp_commit();
    };

    const int wm = (wid & 3) * 32;
    const int wn = (wid >> 2) * 64;
    float acc[2][8][4] = {};

    load_chunk(0, 0);
    load_chunk(1, 1);
    for (int c = 0; c < NCHUNK; ++c) {
        if (c < NCHUNK - 1) cp_wait<1>(); else cp_wait<0>();
        __syncthreads();
        const uint32_t aBase = smem_base + (c % NSTAGE) * BUF_BYTES;
        mma_chunk(aBase, aBase + CHUNK_BYTES, wm, wn, lane, acc);
        if (c + 2 < NCHUNK) load_chunk(c + 2, (c + 2) % NSTAGE);
    }
    __syncthreads();

    float* sSc = (float*)smem;
    if (tid < 128) sSc[tid] = spre;
    __syncthreads();

    const int r    = lane >> 2;
    const int cpos = (lane & 3) * 2;
    #pragma unroll
    for (int mi = 0; mi < 2; ++mi) {
        const int mrow = m0 + wm + mi * 16 + r;
        float* o0 = out + ((size_t)b * HW + mrow) * HW + n0 + wn;
        float* o1 = o0 + (size_t)8 * HW;
        #pragma unroll
        for (int nj = 0; nj < 8; ++nj) {
            const int nc = wn + nj * 8 + cpos;
            const float s0 = sSc[nc], s1 = sSc[nc + 1];
            float2 v0 = make_float2(acc[mi][nj][0] * s0, acc[mi][nj][1] * s1);
            float2 v1 = make_float2(acc[mi][nj][2] * s0, acc[mi][nj][3] * s1);
            *(float2*)&o0[nj * 8 + cpos] = v0;
            *(float2*)&o1[nj * 8 + cpos] = v1;
        }
    }
}

// ---------------------------------------------------------------------------
extern "C" void kernel_launch(void* const* d_in, const int* in_sizes, int n_in,
                              void* d_out, int out_size)
{
    const float* A = (const float*)d_in[0];
    const float* B = (const float*)d_in[1];
    float* out = (float*)d_out;

    static bool init = false;
    if (!init) {
        init = true;
        cudaFuncSetAttribute(corr_mma_kernel,
                             cudaFuncAttributeMaxDynamicSharedMemorySize, SMEM_AUX);
        cudaFuncSetAttribute(gram_mma_kernel,
                             cudaFuncAttributeMaxDynamicSharedMemorySize, SMEM_AUX);
        cudaFuncSetAttribute(qrow_mma_kernel,
                             cudaFuncAttributeMaxDynamicSharedMemorySize, SMEM_AUX);
    }

    convertAB_kernel<<<dim3(HW / 32, CH / 64, BATCH), 256>>>(A, B);
    gram_mma_kernel<<<dim3(3, 1, BATCH * GSLICES), 256, SMEM_AUX>>>();
    greduce_kernel<<<384, 256>>>();
    qrow_mma_kernel<<<dim3(2, HW / 128, BATCH), 256, SMEM_AUX>>>();
    corr_mma_kernel<<<dim3(HW / 128, HW / 128, BATCH), 256, SMEM_AUX>>>(out);
}